// round 6
// baseline (speedup 1.0000x reference)
#include <cuda_runtime.h>
#include <math.h>

#define HH 128
#define WW 128
#define NN 16384          // H*W
#define BB 2
#define DD 32
#define QQ 128
#define MM 16
#define EPSF 1e-8f

// ---------------- scratch (static device allocations; no cudaMalloc) --------
__device__ float g_feat1[BB*NN*DD];
__device__ float g_k   [BB*NN*DD];   // pre-normalized k-hat
__device__ float g_q   [BB*NN*DD];   // pre-normalized q-hat
__device__ float g_w   [BB*NN*25];   // unnormalized exp(cos) weights, [b][pixel][tap]
__device__ float g_hA  [BB*NN*QQ];
__device__ float g_hB  [BB*NN*QQ];

// ---------------- conv1: (B,H,W,3) -> relu -> (B,H,W,32) --------------------
__global__ void conv1_k(const float* __restrict__ x,
                        const float* __restrict__ w,
                        const float* __restrict__ bias) {
    __shared__ float sw[3*3*3*32];
    __shared__ float sb[32];
    for (int t = threadIdx.x; t < 864; t += 512) sw[t] = w[t];
    if (threadIdx.x < 32) sb[threadIdx.x] = bias[threadIdx.x];
    __syncthreads();

    int gid = blockIdx.x * 16 + (threadIdx.x >> 5);   // pixel in [0, B*N)
    int co  = threadIdx.x & 31;
    int b = gid >> 14, p = gid & (NN-1);
    int i = p >> 7, j = p & 127;

    float acc = sb[co];
    #pragma unroll
    for (int ky = 0; ky < 3; ky++) {
        int yi = i + ky - 1;
        if ((unsigned)yi >= HH) continue;
        #pragma unroll
        for (int kx = 0; kx < 3; kx++) {
            int xj = j + kx - 1;
            if ((unsigned)xj >= WW) continue;
            const float* xp = x + ((size_t)((b << 14) | (yi << 7) | xj)) * 3;
            const float* wp = sw + (ky*3 + kx) * 3 * 32;
            #pragma unroll
            for (int ci = 0; ci < 3; ci++) acc += xp[ci] * wp[ci*32 + co];
        }
    }
    g_feat1[(size_t)gid*32 + co] = fmaxf(acc, 0.f);
}

// ------- conv2 + fused k/q projection + normalization (k-hat, q-hat) --------
__global__ void conv2kq_k(const float* __restrict__ w,
                          const float* __restrict__ bias,
                          const float* __restrict__ wk,
                          const float* __restrict__ bk,
                          const float* __restrict__ wq) {
    __shared__ float sw[3*3*32*32];
    __shared__ float swk[1024], swq[1024];
    __shared__ float sb[32], sbk[32];
    for (int t = threadIdx.x; t < 9216; t += 512) sw[t] = w[t];
    for (int t = threadIdx.x; t < 1024; t += 512) { swk[t] = wk[t]; swq[t] = wq[t]; }
    if (threadIdx.x < 32) { sb[threadIdx.x] = bias[threadIdx.x]; sbk[threadIdx.x] = bk[threadIdx.x]; }
    __syncthreads();

    int gid = blockIdx.x * 16 + (threadIdx.x >> 5);
    int co  = threadIdx.x & 31;
    int b = gid >> 14, p = gid & (NN-1);
    int i = p >> 7, j = p & 127;

    float acc = sb[co];
    #pragma unroll
    for (int ky = 0; ky < 3; ky++) {
        int yi = i + ky - 1;
        if ((unsigned)yi >= HH) continue;
        #pragma unroll
        for (int kx = 0; kx < 3; kx++) {
            int xj = j + kx - 1;
            if ((unsigned)xj >= WW) continue;
            const float* fin = g_feat1 + ((size_t)((b << 14) | (yi << 7) | xj)) * 32;
            const float* wp  = sw + (ky*3 + kx) * 32 * 32;
            #pragma unroll
            for (int ci = 0; ci < 32; ci++) acc += fin[ci] * wp[ci*32 + co];
        }
    }
    float fv = fmaxf(acc, 0.f);          // feat2 value for channel co (stays in reg)

    float ka = sbk[co], qa = 0.f;
    #pragma unroll
    for (int ci = 0; ci < 32; ci++) {
        float f = __shfl_sync(0xffffffffu, fv, ci);
        ka += f * swk[ci*32 + co];
        qa += f * swq[ci*32 + co];
    }
    float ks = ka*ka, qs = qa*qa;
    #pragma unroll
    for (int o = 16; o; o >>= 1) {
        ks += __shfl_xor_sync(0xffffffffu, ks, o);
        qs += __shfl_xor_sync(0xffffffffu, qs, o);
    }
    // pre-normalize: cosine sim becomes a plain dot product downstream.
    float kinv = rsqrtf(fmaxf(ks, 1e-30f));
    float qinv = rsqrtf(fmaxf(qs, 1e-30f));
    g_k[(size_t)gid*32 + co] = ka * kinv;
    g_q[(size_t)gid*32 + co] = qa * qinv;
}

// ---------------- edge weights: exp(dot(q-hat, k-hat)), tile-based ----------
__global__ void edgew_k() {
    __shared__ float sk[32*145];    // [c][halo_pixel], padded stride
    __shared__ float sq[64*32];     // [tile_pixel][c]

    int b = blockIdx.z;
    int ti0 = blockIdx.y << 3, tj0 = blockIdx.x << 3;
    int tid = threadIdx.x;
    size_t bbase = (size_t)b << 14;

    // k halo: 144 pixels x 32 ch, transposed on the fly
    for (int t = tid; t < 1152; t += 256) {
        int hp = t >> 3, c4 = t & 7;
        int hr = hp / 12, hc = hp - hr*12;
        int gi = min(max(ti0 + hr - 2, 0), HH-1);
        int gj = min(max(tj0 + hc - 2, 0), WW-1);
        float4 v = ((const float4*)(g_k + (bbase + (gi << 7) + gj) * 32))[c4];
        sk[(c4*4+0)*145 + hp] = v.x;
        sk[(c4*4+1)*145 + hp] = v.y;
        sk[(c4*4+2)*145 + hp] = v.z;
        sk[(c4*4+3)*145 + hp] = v.w;
    }
    // q tile: 64 pixels x 32 ch, straight
    for (int t = tid; t < 512; t += 256) {
        int p = t >> 3, c4 = t & 7;
        int gi = ti0 + (p >> 3), gj = tj0 + (p & 7);
        ((float4*)sq)[t] = ((const float4*)(g_q + (bbase + (gi << 7) + gj) * 32))[c4];
    }
    __syncthreads();

    int lane = tid & 31, a = tid >> 5;          // warp = tile row a
    int d = min(lane, 24);
    int dr = d / 5, dc = d - dr*5;

    for (int cc = 0; cc < 8; cc++) {
        int p = a*8 + cc;
        int hidx = (a + dr)*12 + (cc + dc);
        const float* skp = sk + hidx;
        const float* sqp = sq + p*32;
        float s = 0.f;
        #pragma unroll
        for (int c = 0; c < 32; c++) s += sqp[c] * skp[c*145];
        if (lane < 25) {
            size_t gp = bbase + ((ti0 + a) << 7) + (tj0 + cc);
            g_w[gp*25 + lane] = __expf(s);
        }
    }
}

// ---------------- propagation: weighted 5x5 stencil + L2-normalize ----------
// 8x8 tile / block; 128 channels as TWO sequential 64-ch chunks sharing one
// 12x12x64 halo (36.9KB). Weights staged as PRE-DUPLICATED f32x2 pairs, row
// layout (w0,w0,w1,w1)(w2,w2,w3,w3)(w4,w4): each (output,halo-row) is
// 2x LDS.128 + 1x LDS.64 feeding fma.rn.f32x2 directly -- no mov.b64 packing.
// Chunk-1 halo lines are L1-prefetched during the chunk-0 halo load, so the
// post-barrier LDG burst of chunk 1 hits L1 instead of L2.
#define PROP_SMEM_FLOATS (144*64 + 64*60)
__global__ __launch_bounds__(256, 4) void prop_k(const float* __restrict__ hinit, int it) {
    extern __shared__ float sh[];                    // halo: 144 px x 32 float2
    float* shw = sh + 144*64;                        // weights: 64 px x 30 float2

    const float* hin = (it == 0) ? hinit : ((it & 1) ? g_hA : g_hB);
    float*       hout = (it & 1) ? g_hB : g_hA;

    int b = blockIdx.z;
    int ti0 = blockIdx.y << 3, tj0 = blockIdx.x << 3;
    int tid = threadIdx.x;
    int lane = tid & 31, c = tid >> 5;               // warp = tile column

    const float* hb = hin + ((size_t)b << 21);       // b*N*128
    float* hob = hout + ((size_t)b << 21);

    // stage weights once (valid across both chunks): duplicated (w,w) pairs,
    // row stride 6 float2 (48B) so rows are 16B-aligned for LDS.128.
    const float* wb = g_w + ((size_t)b << 14) * 25;
    for (int t = tid; t < 1600; t += 256) {
        int op = t / 25, d = t - op*25;
        int a = op >> 3, cc = op & 7;
        int r = d / 5, cl = d - r*5;
        float w = wb[(size_t)(((ti0 + a) << 7) | (tj0 + cc)) * 25 + d];
        ((float2*)shw)[op*30 + r*6 + cl] = make_float2(w, w);
    }

    const unsigned long long* sh64  = (const unsigned long long*)sh;
    const unsigned long long* shw64 = (const unsigned long long*)shw;

    unsigned long long acc[2][8];

    #pragma unroll
    for (int chunk = 0; chunk < 2; chunk++) {
        if (chunk) __syncthreads();                  // protect halo before overwrite
        // halo for this 64-ch chunk: 144 px x 16 float4
        for (int t = tid; t < 144*16; t += 256) {
            int prow = t >> 4, f4 = t & 15;
            int hr = prow / 12, hc = prow - hr*12;
            int gi = min(max(ti0 + hr - 2, 0), HH-1);
            int gj = min(max(tj0 + hc - 2, 0), WW-1);
            const float* gp = hb + ((size_t)((gi << 7) + gj) << 7) + chunk*64;
            ((float4*)sh)[t] = ((const float4*)gp)[f4];
            if (chunk == 0) {   // warm L1 for chunk 1's post-barrier burst
                asm volatile("prefetch.global.L1 [%0];" :: "l"(gp + 64 + f4*4));
            }
        }
        __syncthreads();

        #pragma unroll
        for (int a = 0; a < 8; a++) acc[chunk][a] = 0ull;

        #pragma unroll
        for (int hr = 0; hr < 12; hr++) {
            // cache the 5 halo values (dj = 0..4) for this row in registers
            unsigned long long hv[5];
            #pragma unroll
            for (int dj = 0; dj < 5; dj++)
                hv[dj] = sh64[(hr*12 + c + dj)*32 + lane];

            #pragma unroll
            for (int a = 0; a < 8; a++) {
                if (a > hr || a + 4 < hr) continue;      // compile-time pruned
                const unsigned long long* wr = shw64 + (a*8 + c)*30 + (hr - a)*6;
                ulonglong2 p01 = *(const ulonglong2*)(wr);      // (w0,w0),(w1,w1)
                ulonglong2 p23 = *(const ulonglong2*)(wr + 2);  // (w2,w2),(w3,w3)
                unsigned long long p4 = wr[4];                  // (w4,w4)
                asm("fma.rn.f32x2 %0, %1, %2, %0;" : "+l"(acc[chunk][a]) : "l"(hv[0]), "l"(p01.x));
                asm("fma.rn.f32x2 %0, %1, %2, %0;" : "+l"(acc[chunk][a]) : "l"(hv[1]), "l"(p01.y));
                asm("fma.rn.f32x2 %0, %1, %2, %0;" : "+l"(acc[chunk][a]) : "l"(hv[2]), "l"(p23.x));
                asm("fma.rn.f32x2 %0, %1, %2, %0;" : "+l"(acc[chunk][a]) : "l"(hv[3]), "l"(p23.y));
                asm("fma.rn.f32x2 %0, %1, %2, %0;" : "+l"(acc[chunk][a]) : "l"(hv[4]), "l"(p4));
            }
        }
    }

    #pragma unroll
    for (int a = 0; a < 8; a++) {
        float x0, y0, x1, y1;
        asm("mov.b64 {%0,%1}, %2;" : "=f"(x0), "=f"(y0) : "l"(acc[0][a]));
        asm("mov.b64 {%0,%1}, %2;" : "=f"(x1), "=f"(y1) : "l"(acc[1][a]));
        float ss = x0*x0 + y0*y0 + x1*x1 + y1*y1;
        #pragma unroll
        for (int o = 16; o; o >>= 1) ss += __shfl_xor_sync(0xffffffffu, ss, o);
        float inv = 1.f / (sqrtf(ss) + EPSF);
        float* po = hob + ((size_t)(((ti0 + a) << 7) | (tj0 + c)) << 7);
        ((float2*)po)[lane]      = make_float2(x0*inv, y0*inv);
        ((float2*)po)[32 + lane] = make_float2(x1*inv, y1*inv);
    }
}

// ---------------- mask head: h @ w_mask, softmax over M, NCHW out -----------
__global__ void masks_k(const float* __restrict__ wm, float* __restrict__ out) {
    __shared__ float swm[QQ*MM];
    for (int t = threadIdx.x; t < QQ*MM; t += 256) swm[t] = wm[t];
    __syncthreads();

    int gid = blockIdx.x * 256 + threadIdx.x;   // [0, B*N)
    int b = gid >> 14, p = gid & (NN-1);
    const float* hr = g_hB + (size_t)gid * QQ;  // 32 iterations -> final in hB

    float lg[MM];
    #pragma unroll
    for (int m = 0; m < MM; m++) lg[m] = 0.f;
    for (int q = 0; q < QQ; q++) {
        float hv = hr[q];
        #pragma unroll
        for (int m = 0; m < MM; m++) lg[m] += hv * swm[q*MM + m];
    }
    float mx = lg[0];
    #pragma unroll
    for (int m = 1; m < MM; m++) mx = fmaxf(mx, lg[m]);
    float s = 0.f;
    #pragma unroll
    for (int m = 0; m < MM; m++) { lg[m] = __expf(lg[m] - mx); s += lg[m]; }
    float r = 1.f / s;
    #pragma unroll
    for (int m = 0; m < MM; m++)
        out[(((size_t)(b*MM + m)) << 14) + p] = lg[m] * r;
}

// ---------------- launch ----------------------------------------------------
extern "C" void kernel_launch(void* const* d_in, const int* in_sizes, int n_in,
                              void* d_out, int out_size) {
    const float* x    = (const float*)d_in[0];
    // d_in[1] = edges (int32) — edge structure is analytic, unused
    const float* wc1  = (const float*)d_in[2];
    const float* bc1  = (const float*)d_in[3];
    const float* wc2  = (const float*)d_in[4];
    const float* bc2  = (const float*)d_in[5];
    const float* wk   = (const float*)d_in[6];
    const float* bk   = (const float*)d_in[7];
    const float* wq   = (const float*)d_in[8];
    const float* init = (const float*)d_in[9];
    const float* wm   = (const float*)d_in[10];
    float* out = (float*)d_out;

    cudaFuncSetAttribute(prop_k, cudaFuncAttributeMaxDynamicSharedMemorySize,
                         PROP_SMEM_FLOATS * (int)sizeof(float));

    conv1_k  <<<BB*NN*32/512, 512>>>(x, wc1, bc1);
    conv2kq_k<<<BB*NN*32/512, 512>>>(wc2, bc2, wk, bk, wq);
    edgew_k  <<<dim3(WW/8, HH/8, BB), 256>>>();

    for (int it = 0; it < 32; it++) {
        prop_k<<<dim3(WW/8, HH/8, BB), 256,
                 PROP_SMEM_FLOATS * sizeof(float)>>>(init, it);
    }
    masks_k<<<BB*NN/256, 256>>>(wm, out);
}

// round 7
// speedup vs baseline: 1.3039x; 1.3039x over previous
#include <cuda_runtime.h>
#include <math.h>

#define HH 128
#define WW 128
#define NN 16384          // H*W
#define BB 2
#define DD 32
#define QQ 128
#define MM 16
#define EPSF 1e-8f

// ---------------- scratch (static device allocations; no cudaMalloc) --------
__device__ float g_feat1[BB*NN*DD];
__device__ float g_k   [BB*NN*DD];   // pre-normalized k-hat
__device__ float g_q   [BB*NN*DD];   // pre-normalized q-hat
__device__ float g_w   [BB*NN*25];   // unnormalized exp(cos) weights, [b][pixel][tap]
__device__ float g_hA  [BB*NN*QQ];
__device__ float g_hB  [BB*NN*QQ];

// ---------------- conv1: (B,H,W,3) -> relu -> (B,H,W,32) --------------------
__global__ void conv1_k(const float* __restrict__ x,
                        const float* __restrict__ w,
                        const float* __restrict__ bias) {
    __shared__ float sw[3*3*3*32];
    __shared__ float sb[32];
    for (int t = threadIdx.x; t < 864; t += 512) sw[t] = w[t];
    if (threadIdx.x < 32) sb[threadIdx.x] = bias[threadIdx.x];
    __syncthreads();

    int gid = blockIdx.x * 16 + (threadIdx.x >> 5);   // pixel in [0, B*N)
    int co  = threadIdx.x & 31;
    int b = gid >> 14, p = gid & (NN-1);
    int i = p >> 7, j = p & 127;

    float acc = sb[co];
    #pragma unroll
    for (int ky = 0; ky < 3; ky++) {
        int yi = i + ky - 1;
        if ((unsigned)yi >= HH) continue;
        #pragma unroll
        for (int kx = 0; kx < 3; kx++) {
            int xj = j + kx - 1;
            if ((unsigned)xj >= WW) continue;
            const float* xp = x + ((size_t)((b << 14) | (yi << 7) | xj)) * 3;
            const float* wp = sw + (ky*3 + kx) * 3 * 32;
            #pragma unroll
            for (int ci = 0; ci < 3; ci++) acc += xp[ci] * wp[ci*32 + co];
        }
    }
    g_feat1[(size_t)gid*32 + co] = fmaxf(acc, 0.f);
}

// ------- conv2 + fused k/q projection + normalization (k-hat, q-hat) --------
__global__ void conv2kq_k(const float* __restrict__ w,
                          const float* __restrict__ bias,
                          const float* __restrict__ wk,
                          const float* __restrict__ bk,
                          const float* __restrict__ wq) {
    __shared__ float sw[3*3*32*32];
    __shared__ float swk[1024], swq[1024];
    __shared__ float sb[32], sbk[32];
    for (int t = threadIdx.x; t < 9216; t += 512) sw[t] = w[t];
    for (int t = threadIdx.x; t < 1024; t += 512) { swk[t] = wk[t]; swq[t] = wq[t]; }
    if (threadIdx.x < 32) { sb[threadIdx.x] = bias[threadIdx.x]; sbk[threadIdx.x] = bk[threadIdx.x]; }
    __syncthreads();

    int gid = blockIdx.x * 16 + (threadIdx.x >> 5);
    int co  = threadIdx.x & 31;
    int b = gid >> 14, p = gid & (NN-1);
    int i = p >> 7, j = p & 127;

    float acc = sb[co];
    #pragma unroll
    for (int ky = 0; ky < 3; ky++) {
        int yi = i + ky - 1;
        if ((unsigned)yi >= HH) continue;
        #pragma unroll
        for (int kx = 0; kx < 3; kx++) {
            int xj = j + kx - 1;
            if ((unsigned)xj >= WW) continue;
            const float* fin = g_feat1 + ((size_t)((b << 14) | (yi << 7) | xj)) * 32;
            const float* wp  = sw + (ky*3 + kx) * 32 * 32;
            #pragma unroll
            for (int ci = 0; ci < 32; ci++) acc += fin[ci] * wp[ci*32 + co];
        }
    }
    float fv = fmaxf(acc, 0.f);          // feat2 value for channel co (stays in reg)

    float ka = sbk[co], qa = 0.f;
    #pragma unroll
    for (int ci = 0; ci < 32; ci++) {
        float f = __shfl_sync(0xffffffffu, fv, ci);
        ka += f * swk[ci*32 + co];
        qa += f * swq[ci*32 + co];
    }
    float ks = ka*ka, qs = qa*qa;
    #pragma unroll
    for (int o = 16; o; o >>= 1) {
        ks += __shfl_xor_sync(0xffffffffu, ks, o);
        qs += __shfl_xor_sync(0xffffffffu, qs, o);
    }
    // pre-normalize: cosine sim becomes a plain dot product downstream.
    float kinv = rsqrtf(fmaxf(ks, 1e-30f));
    float qinv = rsqrtf(fmaxf(qs, 1e-30f));
    g_k[(size_t)gid*32 + co] = ka * kinv;
    g_q[(size_t)gid*32 + co] = qa * qinv;
}

// ---------------- edge weights: exp(dot(q-hat, k-hat)), tile-based ----------
__global__ void edgew_k() {
    __shared__ float sk[32*145];    // [c][halo_pixel], padded stride
    __shared__ float sq[64*32];     // [tile_pixel][c]

    int b = blockIdx.z;
    int ti0 = blockIdx.y << 3, tj0 = blockIdx.x << 3;
    int tid = threadIdx.x;
    size_t bbase = (size_t)b << 14;

    // k halo: 144 pixels x 32 ch, transposed on the fly
    for (int t = tid; t < 1152; t += 256) {
        int hp = t >> 3, c4 = t & 7;
        int hr = hp / 12, hc = hp - hr*12;
        int gi = min(max(ti0 + hr - 2, 0), HH-1);
        int gj = min(max(tj0 + hc - 2, 0), WW-1);
        float4 v = ((const float4*)(g_k + (bbase + (gi << 7) + gj) * 32))[c4];
        sk[(c4*4+0)*145 + hp] = v.x;
        sk[(c4*4+1)*145 + hp] = v.y;
        sk[(c4*4+2)*145 + hp] = v.z;
        sk[(c4*4+3)*145 + hp] = v.w;
    }
    // q tile: 64 pixels x 32 ch, straight
    for (int t = tid; t < 512; t += 256) {
        int p = t >> 3, c4 = t & 7;
        int gi = ti0 + (p >> 3), gj = tj0 + (p & 7);
        ((float4*)sq)[t] = ((const float4*)(g_q + (bbase + (gi << 7) + gj) * 32))[c4];
    }
    __syncthreads();

    int lane = tid & 31, a = tid >> 5;          // warp = tile row a
    int d = min(lane, 24);
    int dr = d / 5, dc = d - dr*5;

    for (int cc = 0; cc < 8; cc++) {
        int p = a*8 + cc;
        int hidx = (a + dr)*12 + (cc + dc);
        const float* skp = sk + hidx;
        const float* sqp = sq + p*32;
        float s = 0.f;
        #pragma unroll
        for (int c = 0; c < 32; c++) s += sqp[c] * skp[c*145];
        if (lane < 25) {
            size_t gp = bbase + ((ti0 + a) << 7) + (tj0 + cc);
            g_w[gp*25 + lane] = __expf(s);
        }
    }
}

// ---------------- propagation: weighted 5x5 stencil + L2-normalize ----------
// 8x8 tile / block; 128 channels as two 64-ch chunks, lane = channel pair.
// NO halo smem, NO mid-kernel barriers: each warp (tile column c) reads its
// 5-column x 12-row window straight from global with LDG.64 (256B coalesced);
// the 5x intra-block pixel reuse is served by L1D, and without barrier
// convoys the L2-miss latency of first-touch lines overlaps across warps.
// Weights: R5's measured-best scheme — scalar row-padded smem (10.2KB, one
// startup sync), LDS.128+LDS.32 per (output,row), mov.b64 dup into f32x2.
#define PROP_SMEM_FLOATS (64*40)
__global__ __launch_bounds__(256, 4) void prop_k(const float* __restrict__ hinit, int it) {
    __shared__ float shw[PROP_SMEM_FLOATS];          // weights: 64 px x 40 floats

    const float* hin = (it == 0) ? hinit : ((it & 1) ? g_hA : g_hB);
    float*       hout = (it & 1) ? g_hB : g_hA;

    int b = blockIdx.z;
    int ti0 = blockIdx.y << 3, tj0 = blockIdx.x << 3;
    int tid = threadIdx.x;
    int lane = tid & 31, c = tid >> 5;               // warp = tile column

    const float* hb = hin + ((size_t)b << 21);       // b*N*128
    float* hob = hout + ((size_t)b << 21);

    // stage weights (scalar, row-padded to 8 floats for aligned LDS.128)
    const float* wb = g_w + ((size_t)b << 14) * 25;
    for (int t = tid; t < 1600; t += 256) {
        int op = t / 25, d = t - op*25;
        int a = op >> 3, cc = op & 7;
        int r = d / 5, cl = d - r*5;
        shw[op*40 + r*8 + cl] =
            wb[(size_t)(((ti0 + a) << 7) | (tj0 + cc)) * 25 + d];
    }
    __syncthreads();

    unsigned long long acc[2][8];
    #pragma unroll
    for (int ch = 0; ch < 2; ch++)
        #pragma unroll
        for (int a = 0; a < 8; a++) acc[ch][a] = 0ull;

    #pragma unroll
    for (int chunk = 0; chunk < 2; chunk++) {
        const float* hcb = hb + chunk*64 + 2*lane;   // lane's channel pair
        #pragma unroll
        for (int hr = 0; hr < 12; hr++) {
            int gi = min(max(ti0 + hr - 2, 0), HH-1);
            const float* rowp = hcb + ((size_t)gi << 14);   // row base (gi*128*128)
            // 5 halo pixels for this row, direct from global (L1-cached reuse)
            unsigned long long hv[5];
            #pragma unroll
            for (int dj = 0; dj < 5; dj++) {
                int gj = min(max(tj0 + c + dj - 2, 0), WW-1);
                hv[dj] = *(const unsigned long long*)(rowp + ((size_t)gj << 7));
            }
            #pragma unroll
            for (int a = 0; a < 8; a++) {
                if (a > hr || a + 4 < hr) continue;      // compile-time pruned
                const float* wr = shw + (a*8 + c)*40 + (hr - a)*8;
                float4 w03 = *(const float4*)wr;         // taps 0-3 (16B aligned)
                float  w4  = wr[4];                      // tap 4
                unsigned long long W0, W1, W2, W3, W4;
                asm("mov.b64 %0,{%1,%1};" : "=l"(W0) : "f"(w03.x));
                asm("mov.b64 %0,{%1,%1};" : "=l"(W1) : "f"(w03.y));
                asm("mov.b64 %0,{%1,%1};" : "=l"(W2) : "f"(w03.z));
                asm("mov.b64 %0,{%1,%1};" : "=l"(W3) : "f"(w03.w));
                asm("mov.b64 %0,{%1,%1};" : "=l"(W4) : "f"(w4));
                asm("fma.rn.f32x2 %0, %1, %2, %0;" : "+l"(acc[chunk][a]) : "l"(hv[0]), "l"(W0));
                asm("fma.rn.f32x2 %0, %1, %2, %0;" : "+l"(acc[chunk][a]) : "l"(hv[1]), "l"(W1));
                asm("fma.rn.f32x2 %0, %1, %2, %0;" : "+l"(acc[chunk][a]) : "l"(hv[2]), "l"(W2));
                asm("fma.rn.f32x2 %0, %1, %2, %0;" : "+l"(acc[chunk][a]) : "l"(hv[3]), "l"(W3));
                asm("fma.rn.f32x2 %0, %1, %2, %0;" : "+l"(acc[chunk][a]) : "l"(hv[4]), "l"(W4));
            }
        }
    }

    #pragma unroll
    for (int a = 0; a < 8; a++) {
        float x0, y0, x1, y1;
        asm("mov.b64 {%0,%1}, %2;" : "=f"(x0), "=f"(y0) : "l"(acc[0][a]));
        asm("mov.b64 {%0,%1}, %2;" : "=f"(x1), "=f"(y1) : "l"(acc[1][a]));
        float ss = x0*x0 + y0*y0 + x1*x1 + y1*y1;
        #pragma unroll
        for (int o = 16; o; o >>= 1) ss += __shfl_xor_sync(0xffffffffu, ss, o);
        float inv = 1.f / (sqrtf(ss) + EPSF);
        float* po = hob + ((size_t)(((ti0 + a) << 7) | (tj0 + c)) << 7);
        ((float2*)po)[lane]      = make_float2(x0*inv, y0*inv);
        ((float2*)po)[32 + lane] = make_float2(x1*inv, y1*inv);
    }
}

// ---------------- mask head: h @ w_mask, softmax over M, NCHW out -----------
__global__ void masks_k(const float* __restrict__ wm, float* __restrict__ out) {
    __shared__ float swm[QQ*MM];
    for (int t = threadIdx.x; t < QQ*MM; t += 256) swm[t] = wm[t];
    __syncthreads();

    int gid = blockIdx.x * 256 + threadIdx.x;   // [0, B*N)
    int b = gid >> 14, p = gid & (NN-1);
    const float* hr = g_hB + (size_t)gid * QQ;  // 32 iterations -> final in hB

    float lg[MM];
    #pragma unroll
    for (int m = 0; m < MM; m++) lg[m] = 0.f;
    for (int q = 0; q < QQ; q++) {
        float hv = hr[q];
        #pragma unroll
        for (int m = 0; m < MM; m++) lg[m] += hv * swm[q*MM + m];
    }
    float mx = lg[0];
    #pragma unroll
    for (int m = 1; m < MM; m++) mx = fmaxf(mx, lg[m]);
    float s = 0.f;
    #pragma unroll
    for (int m = 0; m < MM; m++) { lg[m] = __expf(lg[m] - mx); s += lg[m]; }
    float r = 1.f / s;
    #pragma unroll
    for (int m = 0; m < MM; m++)
        out[(((size_t)(b*MM + m)) << 14) + p] = lg[m] * r;
}

// ---------------- launch ----------------------------------------------------
extern "C" void kernel_launch(void* const* d_in, const int* in_sizes, int n_in,
                              void* d_out, int out_size) {
    const float* x    = (const float*)d_in[0];
    // d_in[1] = edges (int32) — edge structure is analytic, unused
    const float* wc1  = (const float*)d_in[2];
    const float* bc1  = (const float*)d_in[3];
    const float* wc2  = (const float*)d_in[4];
    const float* bc2  = (const float*)d_in[5];
    const float* wk   = (const float*)d_in[6];
    const float* bk   = (const float*)d_in[7];
    const float* wq   = (const float*)d_in[8];
    const float* init = (const float*)d_in[9];
    const float* wm   = (const float*)d_in[10];
    float* out = (float*)d_out;

    conv1_k  <<<BB*NN*32/512, 512>>>(x, wc1, bc1);
    conv2kq_k<<<BB*NN*32/512, 512>>>(wc2, bc2, wk, bk, wq);
    edgew_k  <<<dim3(WW/8, HH/8, BB), 256>>>();

    for (int it = 0; it < 32; it++) {
        prop_k<<<dim3(WW/8, HH/8, BB), 256>>>(init, it);
    }
    masks_k<<<BB*NN/256, 256>>>(wm, out);
}